// round 1
// baseline (speedup 1.0000x reference)
#include <cuda_runtime.h>
#include <math.h>

// Problem constants (fixed by setup_inputs)
#define NMAX 50000
#define EMAX 400000
#define DD   256
#define HH   128
#define G3   384   // 3*H

// -------- scratch (__device__ globals; no allocation allowed) --------
__device__ float g_HS [NMAX*HH];
__device__ float g_HT [NMAX*HH];
__device__ float g_AGG[NMAX*HH];
__device__ float g_GI [NMAX*G3];
__device__ float g_GH [NMAX*G3];
__device__ float g_AS [NMAX];
__device__ float g_AT [NMAX];
__device__ float g_DEN[NMAX];
__device__ float g_EX [EMAX];
__device__ float g_HOUT_UI[NMAX*HH];  // item (from user->item)
__device__ float g_HOUT_IU[NMAX*HH];  // user (from item->user)
__device__ float g_HOUT_II[NMAX*HH];  // item (from item->item)

// ---------------------------------------------------------------
// Tiled fp32 GEMM: C[M,Nc] = A[M,K] @ B (+bias)
// BT=false: B is [K,Nc] row-major.  BT=true: B is [Nc,K] row-major (B^T applied).
// BM=BN=128, BK=8, 256 threads, 8x8 per thread. Nc must be multiple of 128.
// ---------------------------------------------------------------
template<bool BT, bool HASBIAS>
__global__ void sgemm_k(const float* __restrict__ A, const float* __restrict__ B,
                        const float* __restrict__ bias, float* __restrict__ C,
                        int M, int Nc, int K)
{
    const int BM = 128, BN = 128, BK = 8, TM = 8, TN = 8;
    __shared__ float As[BK][BM];
    __shared__ float Bs[BK][BN];

    const int tid = threadIdx.x;
    const int m0 = blockIdx.x * BM;
    const int n0 = blockIdx.y * BN;
    const int tx = tid & 15;   // 0..15
    const int ty = tid >> 4;   // 0..15

    float acc[TM][TN];
#pragma unroll
    for (int i = 0; i < TM; i++)
#pragma unroll
        for (int j = 0; j < TN; j++) acc[i][j] = 0.f;

    const int aRow = tid >> 1;          // 0..127
    const int aCol = (tid & 1) * 4;     // 0 or 4
    const int bRowN = tid >> 5;         // 0..7   (BT=false)
    const int bColN = (tid & 31) * 4;   // 0..124 (BT=false)
    const int bN    = tid >> 1;         // 0..127 (BT=true)
    const int bKq   = (tid & 1) * 4;    // 0 or 4 (BT=true)

    for (int k0 = 0; k0 < K; k0 += BK) {
        // ---- load A tile (transposed into As[k][m]) ----
        float4 av = make_float4(0.f, 0.f, 0.f, 0.f);
        int gm = m0 + aRow;
        if (gm < M)
            av = *reinterpret_cast<const float4*>(A + (long long)gm * K + k0 + aCol);
        As[aCol + 0][aRow] = av.x;
        As[aCol + 1][aRow] = av.y;
        As[aCol + 2][aRow] = av.z;
        As[aCol + 3][aRow] = av.w;

        // ---- load B tile ----
        if (!BT) {
            float4 bv = *reinterpret_cast<const float4*>(B + (long long)(k0 + bRowN) * Nc + n0 + bColN);
            Bs[bRowN][bColN + 0] = bv.x;
            Bs[bRowN][bColN + 1] = bv.y;
            Bs[bRowN][bColN + 2] = bv.z;
            Bs[bRowN][bColN + 3] = bv.w;
        } else {
            float4 bv = *reinterpret_cast<const float4*>(B + (long long)(n0 + bN) * K + k0 + bKq);
            Bs[bKq + 0][bN] = bv.x;
            Bs[bKq + 1][bN] = bv.y;
            Bs[bKq + 2][bN] = bv.z;
            Bs[bKq + 3][bN] = bv.w;
        }
        __syncthreads();

#pragma unroll
        for (int k = 0; k < BK; k++) {
            float ra[TM], rb[TN];
#pragma unroll
            for (int i = 0; i < TM; i++) ra[i] = As[k][ty * TM + i];
#pragma unroll
            for (int j = 0; j < TN; j++) rb[j] = Bs[k][tx * TN + j];
#pragma unroll
            for (int i = 0; i < TM; i++)
#pragma unroll
                for (int j = 0; j < TN; j++) acc[i][j] += ra[i] * rb[j];
        }
        __syncthreads();
    }

#pragma unroll
    for (int i = 0; i < TM; i++) {
        int gm = m0 + ty * TM + i;
        if (gm >= M) continue;
#pragma unroll
        for (int j = 0; j < TN; j++) {
            int gn = n0 + tx * TN + j;
            float v = acc[i][j];
            if (HASBIAS) v += bias[gn];
            C[(long long)gm * Nc + gn] = v;
        }
    }
}

// ---------------------------------------------------------------
// alpha[n] = dot(feat[n, 0:128], q[0:128])  — one warp per node
// ---------------------------------------------------------------
__global__ void alpha_k(const float* __restrict__ feat, const float* __restrict__ q,
                        float* __restrict__ out, int n)
{
    int warp = (blockIdx.x * blockDim.x + threadIdx.x) >> 5;
    int lane = threadIdx.x & 31;
    if (warp >= n) return;
    float4 a = *reinterpret_cast<const float4*>(feat + (long long)warp * HH + lane * 4);
    float4 b = *reinterpret_cast<const float4*>(q + lane * 4);
    float s = a.x * b.x + a.y * b.y + a.z * b.z + a.w * b.w;
#pragma unroll
    for (int o = 16; o; o >>= 1) s += __shfl_xor_sync(0xffffffffu, s, o);
    if (lane == 0) out[warp] = s;
}

// zero AGG[0:n*H] and DEN[0:n]
__global__ void zero_k(int n)
{
    int i = blockIdx.x * blockDim.x + threadIdx.x;
    if (i < n * HH) g_AGG[i] = 0.f;
    if (i < n)      g_DEN[i] = 0.f;
}

// per-edge: ex = exp(leaky_relu(as[si]+at[ti])); den[ti] += ex
__global__ void edge_logit_k(const int* __restrict__ ei, int E)
{
    int e = blockIdx.x * blockDim.x + threadIdx.x;
    if (e >= E) return;
    int si = ei[e];
    int ti = ei[E + e];
    float l = g_AS[si] + g_AT[ti];
    l = (l > 0.f) ? l : 0.2f * l;
    float ex = expf(l);
    g_EX[e] = ex;
    atomicAdd(&g_DEN[ti], ex);
}

// per-edge scatter: agg[ti,:] += (ex[e]/(den[ti]+eps)) * hs[si,:]  — warp/edge
__global__ void edge_scatter_k(const int* __restrict__ ei, int E)
{
    int gw   = (blockIdx.x * blockDim.x + threadIdx.x) >> 5;
    int lane = threadIdx.x & 31;
    if (gw >= E) return;
    int si = ei[gw];
    int ti = ei[E + gw];
    float c = g_EX[gw] / (g_DEN[ti] + 1e-16f);
    float4 v = *reinterpret_cast<const float4*>(g_HS + (long long)si * HH + lane * 4);
    float* dst = g_AGG + (long long)ti * HH + lane * 4;
    atomicAdd(dst + 0, c * v.x);
    atomicAdd(dst + 1, c * v.y);
    atomicAdd(dst + 2, c * v.z);
    atomicAdd(dst + 3, c * v.w);
}

// GRU elementwise combine: out = (1-z)*n + z*agg
__global__ void gru_k(float* __restrict__ out, int n)
{
    int i = blockIdx.x * blockDim.x + threadIdx.x;
    if (i >= n * HH) return;
    int nn = i / HH, h = i % HH;
    const float* gi = g_GI + (long long)nn * G3;
    const float* gh = g_GH + (long long)nn * G3;
    float r = 1.f / (1.f + expf(-(gi[h] + gh[h])));
    float z = 1.f / (1.f + expf(-(gi[HH + h] + gh[HH + h])));
    float g = tanhf(gi[2 * HH + h] + r * gh[2 * HH + h]);
    float a = g_AGG[i];
    out[i] = (1.f - z) * g + z * a;
}

// out_user = relu(h_user_iu)  (semantic att over single relation is identity)
__global__ void relu_copy_k(float* __restrict__ out, int total)
{
    int i = blockIdx.x * blockDim.x + threadIdx.x;
    if (i < total) out[i] = fmaxf(g_HOUT_IU[i], 0.f);
}

// item semantic attention over {h_item_ui, h_item_ii} then relu — warp/node
__global__ void sem_item_k(float* __restrict__ out, const float* __restrict__ g, int n)
{
    int warp = (blockIdx.x * blockDim.x + threadIdx.x) >> 5;
    int lane = threadIdx.x & 31;
    if (warp >= n) return;
    float4 v0 = *reinterpret_cast<const float4*>(g_HOUT_UI + (long long)warp * HH + lane * 4);
    float4 v1 = *reinterpret_cast<const float4*>(g_HOUT_II + (long long)warp * HH + lane * 4);
    float4 gv = *reinterpret_cast<const float4*>(g + lane * 4);
    float d0 = v0.x * gv.x + v0.y * gv.y + v0.z * gv.z + v0.w * gv.w;
    float d1 = v1.x * gv.x + v1.y * gv.y + v1.z * gv.z + v1.w * gv.w;
#pragma unroll
    for (int o = 16; o; o >>= 1) {
        d0 += __shfl_xor_sync(0xffffffffu, d0, o);
        d1 += __shfl_xor_sync(0xffffffffu, d1, o);
    }
    float a0 = expf(d0), a1 = expf(d1);
    float inv = 1.f / (a0 + a1);
    float w0 = a0 * inv, w1 = a1 * inv;
    float4 o4;
    o4.x = fmaxf(w0 * v0.x + w1 * v1.x, 0.f);
    o4.y = fmaxf(w0 * v0.y + w1 * v1.y, 0.f);
    o4.z = fmaxf(w0 * v0.z + w1 * v1.z, 0.f);
    o4.w = fmaxf(w0 * v0.w + w1 * v1.w, 0.f);
    *reinterpret_cast<float4*>(out + (long long)warp * HH + lane * 4) = o4;
}

// ---------------------------------------------------------------
extern "C" void kernel_launch(void* const* d_in, const int* in_sizes, int n_in,
                              void* d_out, int out_size)
{
    const float* x_user = (const float*)d_in[0];
    const float* x_item = (const float*)d_in[1];
    const int*   ei_ui  = (const int*)d_in[2];
    const int*   ei_iu  = (const int*)d_in[3];
    const int*   ei_ii  = (const int*)d_in[4];

    int N = in_sizes[0] / DD;
    int E = in_sizes[2] / 2;
    if (N > NMAX) N = NMAX;
    if (E > EMAX) E = EMAX;

    float* out = (float*)d_out;

    // device addresses of scratch symbols
    float *pHS, *pHT, *pAGG, *pGI, *pGH, *pAS, *pAT;
    float *pUI, *pIU, *pII;
    cudaGetSymbolAddress((void**)&pHS,  g_HS);
    cudaGetSymbolAddress((void**)&pHT,  g_HT);
    cudaGetSymbolAddress((void**)&pAGG, g_AGG);
    cudaGetSymbolAddress((void**)&pGI,  g_GI);
    cudaGetSymbolAddress((void**)&pGH,  g_GH);
    cudaGetSymbolAddress((void**)&pAS,  g_AS);
    cudaGetSymbolAddress((void**)&pAT,  g_AT);
    cudaGetSymbolAddress((void**)&pUI,  g_HOUT_UI);
    cudaGetSymbolAddress((void**)&pIU,  g_HOUT_IU);
    cudaGetSymbolAddress((void**)&pII,  g_HOUT_II);

    const int mb = (N + 127) / 128;
    dim3 gG1(mb, 1);          // Nc = 128
    dim3 gG2(mb, G3 / 128);   // Nc = 384
    int nwBlocks  = (N * 32 + 255) / 256;     // warp-per-node kernels
    int zBlocks   = (N * HH + 255) / 256;
    int e1Blocks  = (E + 255) / 256;
    int e2Blocks  = (E * 32 + 255) / 256;     // warp-per-edge

    struct RelDesc {
        const float* xs; const float* xt; const int* ei;
        int base;        // d_in index of w_src
        float* hout;
    };
    RelDesc rels[3] = {
        { x_user, x_item, ei_ui,  5, pUI },   // (user -> item)
        { x_item, x_user, ei_iu, 12, pIU },   // (item -> user)
        { x_item, x_item, ei_ii, 19, pII },   // (item -> item)
    };

    for (int r = 0; r < 3; r++) {
        const RelDesc& R = rels[r];
        const float* w_src = (const float*)d_in[R.base + 0];
        const float* w_tgt = (const float*)d_in[R.base + 1];
        const float* q     = (const float*)d_in[R.base + 2];
        const float* wih   = (const float*)d_in[R.base + 3];
        const float* whh   = (const float*)d_in[R.base + 4];
        const float* bih   = (const float*)d_in[R.base + 5];
        const float* bhh   = (const float*)d_in[R.base + 6];

        // hs = xs @ w_src ; ht = xt @ w_tgt
        sgemm_k<false, false><<<gG1, 256>>>(R.xs, w_src, nullptr, pHS, N, HH, DD);
        sgemm_k<false, false><<<gG1, 256>>>(R.xt, w_tgt, nullptr, pHT, N, HH, DD);

        // per-node attention scalars
        alpha_k<<<nwBlocks, 256>>>(pHS, q,      pAS, N);
        alpha_k<<<nwBlocks, 256>>>(pHT, q + HH, pAT, N);

        // zero den + agg
        zero_k<<<zBlocks, 256>>>(N);

        // edge softmax numerators + denominators
        edge_logit_k<<<e1Blocks, 256>>>(R.ei, E);

        // weighted scatter-sum into agg
        edge_scatter_k<<<e2Blocks, 256>>>(R.ei, E);

        // GRU gates: gi = ht@wih^T + bih ; gh = agg@whh^T + bhh
        sgemm_k<true, true><<<gG2, 256>>>(pHT,  wih, bih, pGI, N, G3, HH);
        sgemm_k<true, true><<<gG2, 256>>>(pAGG, whh, bhh, pGH, N, G3, HH);

        // combine
        gru_k<<<zBlocks, 256>>>(R.hout, N);
    }

    // out_user = relu(h_user_iu)
    relu_copy_k<<<zBlocks, 256>>>(out, N * HH);
    // out_item = relu(sem_att([h_item_ui, h_item_ii], g_item))
    const float* g_item = (const float*)d_in[27];
    sem_item_k<<<(N + 7) / 8, 256>>>(out + (long long)N * HH, g_item, N);
}

// round 3
// speedup vs baseline: 1.4877x; 1.4877x over previous
#include <cuda_runtime.h>
#include <cuda_bf16.h>
#include <math.h>
#include <cstdint>

#define NMAX 50000
#define EMAX 400000
#define DD   256
#define HH   128
#define G3   384

// ------------------- scratch (__device__ globals) -------------------
__device__ float g_HS [NMAX*HH];
__device__ float g_HT [NMAX*HH];
__device__ float g_AGG[NMAX*HH];
__device__ float g_GI [NMAX*G3];
__device__ float g_GH [NMAX*G3];
__device__ float g_AS [NMAX];
__device__ float g_AT [NMAX];
__device__ float g_DEN[NMAX];
__device__ float g_EX [EMAX];
__device__ float g_HUI[NMAX*HH];
__device__ float g_HIU[NMAX*HH];
__device__ float g_HII[NMAX*HH];
// pre-split weights bf16 hi/lo. WT: transposed w_src/w_tgt -> [Nc=128][K=256]
// WG: wih/whh already [384][128] ([Nc][K], K contiguous)
__device__ __nv_bfloat16 g_WTh[6*128*256];
__device__ __nv_bfloat16 g_WTl[6*128*256];
__device__ __nv_bfloat16 g_WGh[6*384*128];
__device__ __nv_bfloat16 g_WGl[6*384*128];

// ------------------- small PTX helpers -------------------
__device__ __forceinline__ uint32_t smem_u32(const void* p) {
    uint32_t a;
    asm("{ .reg .u64 t; cvta.to.shared.u64 t, %1; cvt.u32.u64 %0, t; }" : "=r"(a) : "l"(p));
    return a;
}
__device__ __forceinline__ void ldsm4(uint32_t* r, uint32_t addr) {
    asm volatile("ldmatrix.sync.aligned.m8n8.x4.shared.b16 {%0,%1,%2,%3}, [%4];"
                 : "=r"(r[0]), "=r"(r[1]), "=r"(r[2]), "=r"(r[3]) : "r"(addr));
}
__device__ __forceinline__ void mma_bf16(float* d, const uint32_t* a, const uint32_t* b) {
    asm volatile(
        "mma.sync.aligned.m16n8k16.row.col.f32.bf16.bf16.f32 "
        "{%0,%1,%2,%3}, {%4,%5,%6,%7}, {%8,%9}, {%0,%1,%2,%3};"
        : "+f"(d[0]), "+f"(d[1]), "+f"(d[2]), "+f"(d[3])
        : "r"(a[0]), "r"(a[1]), "r"(a[2]), "r"(a[3]), "r"(b[0]), "r"(b[1]));
}

// ------------------- weight prep -------------------
__global__ void prep_wt(const float* __restrict__ w,
                        __nv_bfloat16* __restrict__ oh, __nv_bfloat16* __restrict__ ol)
{
    int i = blockIdx.x * blockDim.x + threadIdx.x;
    if (i >= 128 * 256) return;
    int n = i >> 8, k = i & 255;
    float x = w[k * 128 + n];
    __nv_bfloat16 h = __float2bfloat16(x);
    oh[i] = h;
    ol[i] = __float2bfloat16(x - __bfloat162float(h));
}
__global__ void prep_wg(const float* __restrict__ w,
                        __nv_bfloat16* __restrict__ oh, __nv_bfloat16* __restrict__ ol)
{
    int i = blockIdx.x * blockDim.x + threadIdx.x;
    if (i >= 384 * 128) return;
    float x = w[i];
    __nv_bfloat16 h = __float2bfloat16(x);
    oh[i] = h;
    ol[i] = __float2bfloat16(x - __bfloat162float(h));
}

// ------------------- bf16-split tensor-core GEMM (mma.sync) -------------------
// C[M,Nc] = A[M,K](fp32) @ B, B pre-split bf16 hi/lo in [Nc][K] (K contiguous).
// Emulates fp32: Ah*Bh + Ah*Bl + Al*Bh. CTA tile 128x128, BK=64, 8 warps (32x64 each).
// smem rows padded to 72 b16 (144B) -> ldmatrix conflict-free.
#define SROW 144  // bytes per smem row (72 bf16)
template<bool HASBIAS>
__global__ void __launch_bounds__(256) mm_gemm(
    const float* __restrict__ A,
    const __nv_bfloat16* __restrict__ Bh, const __nv_bfloat16* __restrict__ Bl,
    const float* __restrict__ bias, float* __restrict__ C,
    int M, int Nc, int K)
{
    extern __shared__ char smem[];
    const uint32_t sb = smem_u32(smem);
    const uint32_t sAh = sb;
    const uint32_t sAl = sb + 128 * SROW;
    const uint32_t sBh = sb + 2 * 128 * SROW;
    const uint32_t sBl = sb + 3 * 128 * SROW;

    const int tid  = threadIdx.x;
    const int wid  = tid >> 5;
    const int lane = tid & 31;
    const int warp_m = wid & 3;   // 0..3 -> m offset 32*warp_m
    const int warp_n = wid >> 2;  // 0..1 -> n offset 64*warp_n
    const int m0 = blockIdx.x * 128;
    const int n0 = blockIdx.y * 128;

    float acc[2][8][4];
#pragma unroll
    for (int i = 0; i < 2; i++)
#pragma unroll
        for (int j = 0; j < 8; j++)
#pragma unroll
            for (int t = 0; t < 4; t++) acc[i][j][t] = 0.f;

    const int nchunks = K >> 6;
    for (int kc = 0; kc < nchunks; kc++) {
        const int k0 = kc << 6;

        // ---- A fill: 128 rows x 64 k, fp32 -> bf16 hi/lo ----
        for (int idx = tid; idx < 2048; idx += 256) {
            int row = idx >> 4;
            int q   = idx & 15;                 // float4 index along k
            float4 v = make_float4(0.f, 0.f, 0.f, 0.f);
            if (m0 + row < M)
                v = *reinterpret_cast<const float4*>(A + (size_t)(m0 + row) * K + k0 + q * 4);
            __nv_bfloat16 h0 = __float2bfloat16(v.x);
            __nv_bfloat16 h1 = __float2bfloat16(v.y);
            __nv_bfloat16 h2 = __float2bfloat16(v.z);
            __nv_bfloat16 h3 = __float2bfloat16(v.w);
            __nv_bfloat16 l0 = __float2bfloat16(v.x - __bfloat162float(h0));
            __nv_bfloat16 l1 = __float2bfloat16(v.y - __bfloat162float(h1));
            __nv_bfloat16 l2 = __float2bfloat16(v.z - __bfloat162float(h2));
            __nv_bfloat16 l3 = __float2bfloat16(v.w - __bfloat162float(h3));
            uint2 hp, lp;
            hp.x = ((uint32_t)__bfloat16_as_ushort(h1) << 16) | __bfloat16_as_ushort(h0);
            hp.y = ((uint32_t)__bfloat16_as_ushort(h3) << 16) | __bfloat16_as_ushort(h2);
            lp.x = ((uint32_t)__bfloat16_as_ushort(l1) << 16) | __bfloat16_as_ushort(l0);
            lp.y = ((uint32_t)__bfloat16_as_ushort(l3) << 16) | __bfloat16_as_ushort(l2);
            uint32_t off = row * SROW + q * 8;
            *reinterpret_cast<uint2*>(smem + (sAh - sb) + off) = hp;
            *reinterpret_cast<uint2*>(smem + (sAl - sb) + off) = lp;
        }
        // ---- B fill: 128 rows x 64 k, pre-split bf16, 16B copies ----
        for (int idx = tid; idx < 1024; idx += 256) {
            int row = idx >> 3, q = idx & 7;
            size_t src = (size_t)(n0 + row) * K + k0 + q * 8;
            uint32_t off = row * SROW + q * 16;
            *reinterpret_cast<uint4*>(smem + (sBh - sb) + off) =
                *reinterpret_cast<const uint4*>(Bh + src);
            *reinterpret_cast<uint4*>(smem + (sBl - sb) + off) =
                *reinterpret_cast<const uint4*>(Bl + src);
        }
        __syncthreads();

#pragma unroll
        for (int ks = 0; ks < 4; ks++) {
            // A fragments (2 m-tiles x hi/lo)
            uint32_t afh[2][4], afl[2][4];
            {
                int r  = lane & 15;
                int c8 = lane >> 4;
                uint32_t off = (uint32_t)((warp_m * 32 + r) * SROW + (ks * 16 + c8 * 8) * 2);
                ldsm4(afh[0], sAh + off);
                ldsm4(afh[1], sAh + off + 16 * SROW);
                ldsm4(afl[0], sAl + off);
                ldsm4(afl[1], sAl + off + 16 * SROW);
            }
            // B fragments (8 n-tiles x hi/lo), x4 covers 2 n-tiles
            uint32_t bfh[8][2], bfl[8][2];
            {
                int sub = lane >> 3, wi = lane & 7;
                int n_off = (sub >> 1) * 8 + wi;
                int k_off = ks * 16 + (sub & 1) * 8;
                uint32_t base = (uint32_t)((warp_n * 64 + n_off) * SROW + k_off * 2);
#pragma unroll
                for (int jj = 0; jj < 4; jj++) {
                    uint32_t r4[4];
                    ldsm4(r4, sBh + base + jj * 16 * SROW);
                    bfh[2 * jj][0] = r4[0]; bfh[2 * jj][1] = r4[1];
                    bfh[2 * jj + 1][0] = r4[2]; bfh[2 * jj + 1][1] = r4[3];
                    ldsm4(r4, sBl + base + jj * 16 * SROW);
                    bfl[2 * jj][0] = r4[0]; bfl[2 * jj][1] = r4[1];
                    bfl[2 * jj + 1][0] = r4[2]; bfl[2 * jj + 1][1] = r4[3];
                }
            }
#pragma unroll
            for (int mi = 0; mi < 2; mi++)
#pragma unroll
                for (int j = 0; j < 8; j++) {
                    mma_bf16(acc[mi][j], afh[mi], bfh[j]);
                    mma_bf16(acc[mi][j], afh[mi], bfl[j]);
                    mma_bf16(acc[mi][j], afl[mi], bfh[j]);
                }
        }
        __syncthreads();
    }

    // ---- epilogue ----
#pragma unroll
    for (int mi = 0; mi < 2; mi++) {
        int gr = m0 + warp_m * 32 + mi * 16 + (lane >> 2);
#pragma unroll
        for (int j = 0; j < 8; j++) {
            int gc = n0 + warp_n * 64 + j * 8 + 2 * (lane & 3);
            float b0 = 0.f, b1 = 0.f;
            if (HASBIAS) { b0 = bias[gc]; b1 = bias[gc + 1]; }
            if (gr < M) {
                float2 v = make_float2(acc[mi][j][0] + b0, acc[mi][j][1] + b1);
                *reinterpret_cast<float2*>(C + (size_t)gr * Nc + gc) = v;
            }
            if (gr + 8 < M) {
                float2 v = make_float2(acc[mi][j][2] + b0, acc[mi][j][3] + b1);
                *reinterpret_cast<float2*>(C + (size_t)(gr + 8) * Nc + gc) = v;
            }
        }
    }
}

// ------------------- edge phase + pointwise kernels -------------------
__global__ void alpha_k(const float* __restrict__ feat, const float* __restrict__ q,
                        float* __restrict__ out, int n)
{
    int warp = (blockIdx.x * blockDim.x + threadIdx.x) >> 5;
    int lane = threadIdx.x & 31;
    if (warp >= n) return;
    float4 a = *reinterpret_cast<const float4*>(feat + (long long)warp * HH + lane * 4);
    float4 b = *reinterpret_cast<const float4*>(q + lane * 4);
    float s = a.x * b.x + a.y * b.y + a.z * b.z + a.w * b.w;
#pragma unroll
    for (int o = 16; o; o >>= 1) s += __shfl_xor_sync(0xffffffffu, s, o);
    if (lane == 0) out[warp] = s;
}

__global__ void zero_k(int n)
{
    int i = blockIdx.x * blockDim.x + threadIdx.x;
    if (i < n * HH) g_AGG[i] = 0.f;
    if (i < n)      g_DEN[i] = 0.f;
}

__global__ void edge_logit_k(const int* __restrict__ ei, int E)
{
    int e = blockIdx.x * blockDim.x + threadIdx.x;
    if (e >= E) return;
    int si = ei[e];
    int ti = ei[E + e];
    float l = g_AS[si] + g_AT[ti];
    l = (l > 0.f) ? l : 0.2f * l;
    float ex = expf(l);
    g_EX[e] = ex;
    atomicAdd(&g_DEN[ti], ex);
}

__global__ void edge_scatter_k(const int* __restrict__ ei, int E)
{
    int gw   = (blockIdx.x * blockDim.x + threadIdx.x) >> 5;
    int lane = threadIdx.x & 31;
    if (gw >= E) return;
    int si = ei[gw];
    int ti = ei[E + gw];
    float c = g_EX[gw] / (g_DEN[ti] + 1e-16f);
    float4 v = *reinterpret_cast<const float4*>(g_HS + (long long)si * HH + lane * 4);
    float* dst = g_AGG + (long long)ti * HH + lane * 4;
    atomicAdd(dst + 0, c * v.x);
    atomicAdd(dst + 1, c * v.y);
    atomicAdd(dst + 2, c * v.z);
    atomicAdd(dst + 3, c * v.w);
}

__global__ void gru_k(float* __restrict__ out, int n)
{
    int i = blockIdx.x * blockDim.x + threadIdx.x;
    if (i >= n * HH) return;
    int nn = i / HH, h = i % HH;
    const float* gi = g_GI + (long long)nn * G3;
    const float* gh = g_GH + (long long)nn * G3;
    float r = 1.f / (1.f + expf(-(gi[h] + gh[h])));
    float z = 1.f / (1.f + expf(-(gi[HH + h] + gh[HH + h])));
    float g = tanhf(gi[2 * HH + h] + r * gh[2 * HH + h]);
    float a = g_AGG[i];
    out[i] = (1.f - z) * g + z * a;
}

__global__ void relu_copy_k(float* __restrict__ out, int total)
{
    int i = blockIdx.x * blockDim.x + threadIdx.x;
    if (i < total) out[i] = fmaxf(g_HIU[i], 0.f);
}

__global__ void sem_item_k(float* __restrict__ out, const float* __restrict__ g, int n)
{
    int warp = (blockIdx.x * blockDim.x + threadIdx.x) >> 5;
    int lane = threadIdx.x & 31;
    if (warp >= n) return;
    float4 v0 = *reinterpret_cast<const float4*>(g_HUI + (long long)warp * HH + lane * 4);
    float4 v1 = *reinterpret_cast<const float4*>(g_HII + (long long)warp * HH + lane * 4);
    float4 gv = *reinterpret_cast<const float4*>(g + lane * 4);
    float d0 = v0.x * gv.x + v0.y * gv.y + v0.z * gv.z + v0.w * gv.w;
    float d1 = v1.x * gv.x + v1.y * gv.y + v1.z * gv.z + v1.w * gv.w;
#pragma unroll
    for (int o = 16; o; o >>= 1) {
        d0 += __shfl_xor_sync(0xffffffffu, d0, o);
        d1 += __shfl_xor_sync(0xffffffffu, d1, o);
    }
    float a0 = expf(d0), a1 = expf(d1);
    float inv = 1.f / (a0 + a1);
    float w0 = a0 * inv, w1 = a1 * inv;
    float4 o4;
    o4.x = fmaxf(w0 * v0.x + w1 * v1.x, 0.f);
    o4.y = fmaxf(w0 * v0.y + w1 * v1.y, 0.f);
    o4.z = fmaxf(w0 * v0.z + w1 * v1.z, 0.f);
    o4.w = fmaxf(w0 * v0.w + w1 * v1.w, 0.f);
    *reinterpret_cast<float4*>(out + (long long)warp * HH + lane * 4) = o4;
}

// ---------------------------------------------------------------
extern "C" void kernel_launch(void* const* d_in, const int* in_sizes, int n_in,
                              void* d_out, int out_size)
{
    const float* x_user = (const float*)d_in[0];
    const float* x_item = (const float*)d_in[1];
    const int*   ei_ui  = (const int*)d_in[2];
    const int*   ei_iu  = (const int*)d_in[3];
    const int*   ei_ii  = (const int*)d_in[4];

    int N = in_sizes[0] / DD;
    int E = in_sizes[2] / 2;
    if (N > NMAX) N = NMAX;
    if (E > EMAX) E = EMAX;

    float* out = (float*)d_out;

    float *pHS, *pHT, *pAGG, *pGI, *pGH, *pAS, *pAT;
    float *pUI, *pIU, *pII;
    __nv_bfloat16 *pWTh, *pWTl, *pWGh, *pWGl;
    cudaGetSymbolAddress((void**)&pHS,  g_HS);
    cudaGetSymbolAddress((void**)&pHT,  g_HT);
    cudaGetSymbolAddress((void**)&pAGG, g_AGG);
    cudaGetSymbolAddress((void**)&pGI,  g_GI);
    cudaGetSymbolAddress((void**)&pGH,  g_GH);
    cudaGetSymbolAddress((void**)&pAS,  g_AS);
    cudaGetSymbolAddress((void**)&pAT,  g_AT);
    cudaGetSymbolAddress((void**)&pUI,  g_HUI);
    cudaGetSymbolAddress((void**)&pIU,  g_HIU);
    cudaGetSymbolAddress((void**)&pII,  g_HII);
    cudaGetSymbolAddress((void**)&pWTh, g_WTh);
    cudaGetSymbolAddress((void**)&pWTl, g_WTl);
    cudaGetSymbolAddress((void**)&pWGh, g_WGh);
    cudaGetSymbolAddress((void**)&pWGl, g_WGl);

    const int SMEMSZ = 4 * 128 * SROW;  // 73728
    cudaFuncSetAttribute(mm_gemm<false>, cudaFuncAttributeMaxDynamicSharedMemorySize, SMEMSZ);
    cudaFuncSetAttribute(mm_gemm<true>,  cudaFuncAttributeMaxDynamicSharedMemorySize, SMEMSZ);

    struct RelDesc {
        const float* xs; const float* xt; const int* ei;
        int base;
        float* hout;
    };
    RelDesc rels[3] = {
        { x_user, x_item, ei_ui,  5, pUI },
        { x_item, x_user, ei_iu, 12, pIU },
        { x_item, x_item, ei_ii, 19, pII },
    };

    // ---- weight prep ----
    for (int r = 0; r < 3; r++) {
        const RelDesc& R = rels[r];
        const float* w_src = (const float*)d_in[R.base + 0];
        const float* w_tgt = (const float*)d_in[R.base + 1];
        const float* wih   = (const float*)d_in[R.base + 3];
        const float* whh   = (const float*)d_in[R.base + 4];
        int wt0 = (r * 2 + 0) * 128 * 256;
        int wt1 = (r * 2 + 1) * 128 * 256;
        int wg0 = (r * 2 + 0) * 384 * 128;
        int wg1 = (r * 2 + 1) * 384 * 128;
        prep_wt<<<(128 * 256 + 255) / 256, 256>>>(w_src, pWTh + wt0, pWTl + wt0);
        prep_wt<<<(128 * 256 + 255) / 256, 256>>>(w_tgt, pWTh + wt1, pWTl + wt1);
        prep_wg<<<(384 * 128 + 255) / 256, 256>>>(wih, pWGh + wg0, pWGl + wg0);
        prep_wg<<<(384 * 128 + 255) / 256, 256>>>(whh, pWGh + wg1, pWGl + wg1);
    }

    const int mb = (N + 127) / 128;
    dim3 gG1(mb, 1);
    dim3 gG2(mb, 3);
    int nwBlocks = (N * 32 + 255) / 256;
    int zBlocks  = (N * HH + 255) / 256;
    int e1Blocks = (E + 255) / 256;
    int e2Blocks = (E * 32 + 255) / 256;

    for (int r = 0; r < 3; r++) {
        const RelDesc& R = rels[r];
        const float* q   = (const float*)d_in[R.base + 2];
        const float* bih = (const float*)d_in[R.base + 5];
        const float* bhh = (const float*)d_in[R.base + 6];
        int wt0 = (r * 2 + 0) * 128 * 256;
        int wt1 = (r * 2 + 1) * 128 * 256;
        int wg0 = (r * 2 + 0) * 384 * 128;
        int wg1 = (r * 2 + 1) * 384 * 128;

        // hs = xs @ w_src ; ht = xt @ w_tgt  (tensor cores, 3x bf16 split)
        mm_gemm<false><<<gG1, 256, SMEMSZ>>>(R.xs, pWTh + wt0, pWTl + wt0, nullptr, pHS, N, HH, DD);
        mm_gemm<false><<<gG1, 256, SMEMSZ>>>(R.xt, pWTh + wt1, pWTl + wt1, nullptr, pHT, N, HH, DD);

        alpha_k<<<nwBlocks, 256>>>(pHS, q,      pAS, N);
        alpha_k<<<nwBlocks, 256>>>(pHT, q + HH, pAT, N);

        zero_k<<<zBlocks, 256>>>(N);
        edge_logit_k<<<e1Blocks, 256>>>(R.ei, E);
        edge_scatter_k<<<e2Blocks, 256>>>(R.ei, E);

        // gi = ht @ wih^T + bih ; gh = agg @ whh^T + bhh
        mm_gemm<true><<<gG2, 256, SMEMSZ>>>(pHT,  pWGh + wg0, pWGl + wg0, bih, pGI, N, G3, HH);
        mm_gemm<true><<<gG2, 256, SMEMSZ>>>(pAGG, pWGh + wg1, pWGl + wg1, bhh, pGH, N, G3, HH);

        gru_k<<<zBlocks, 256>>>(R.hout, N);
    }

    relu_copy_k<<<zBlocks, 256>>>(out, N * HH);
    const float* g_item = (const float*)d_in[27];
    sem_item_k<<<(N + 7) / 8, 256>>>(out + (long long)N * HH, g_item, N);
}